// round 5
// baseline (speedup 1.0000x reference)
#include <cuda_runtime.h>
#include <cuda_fp16.h>
#include <cstdint>

#define N_MAX 50000
#define E_MAX 800000

// ---------------- scratch (__device__ globals; no allocs allowed) ----------
__device__ int      g_deg_in[N_MAX];
__device__ int      g_deg_out[N_MAX];
__device__ int      g_row_start[N_MAX + 1];
__device__ int      g_cursor[N_MAX];
__device__ int      g_csr_src[E_MAX];
__device__ float    g_norm_src[N_MAX];
__device__ uint2    g_h16[(size_t)N_MAX * 32];    // fp16 x*norm_src
__device__ uint32_t g_agg[(size_t)N_MAX * 128];   // tf32 bits of aggregated rows

__device__ __forceinline__ uint32_t f2tf32(float v) {
    uint32_t r;
    asm("cvt.rna.tf32.f32 %0, %1;" : "=r"(r) : "f"(v));
    return r;
}

__device__ __forceinline__ void mma_tf32(float c[4], uint32_t a0, uint32_t a1,
                                         uint32_t a2, uint32_t a3,
                                         uint32_t b0, uint32_t b1) {
    asm volatile(
        "mma.sync.aligned.m16n8k8.row.col.f32.tf32.tf32.f32 "
        "{%0,%1,%2,%3}, {%4,%5,%6,%7}, {%8,%9}, {%0,%1,%2,%3};"
        : "+f"(c[0]), "+f"(c[1]), "+f"(c[2]), "+f"(c[3])
        : "r"(a0), "r"(a1), "r"(a2), "r"(a3), "r"(b0), "r"(b1));
}

// ---------------- prep ------------------------------------------------------
__global__ void k_init(int n4) {            // zero deg_in / deg_out, int4-wide
    int i = blockIdx.x * blockDim.x + threadIdx.x;
    int4 z = make_int4(0, 0, 0, 0);
    if (i < n4) {
        reinterpret_cast<int4*>(g_deg_in)[i] = z;
        reinterpret_cast<int4*>(g_deg_out)[i] = z;
    }
}

__global__ void k_count(const int* __restrict__ ei, int e4, int e) {
    int i = blockIdx.x * blockDim.x + threadIdx.x;
    if (i < e4) {
        int4 s = reinterpret_cast<const int4*>(ei)[i];
        int4 d = reinterpret_cast<const int4*>(ei + e)[i];
        atomicAdd(&g_deg_out[s.x], 1); atomicAdd(&g_deg_out[s.y], 1);
        atomicAdd(&g_deg_out[s.z], 1); atomicAdd(&g_deg_out[s.w], 1);
        atomicAdd(&g_deg_in[d.x], 1);  atomicAdd(&g_deg_in[d.y], 1);
        atomicAdd(&g_deg_in[d.z], 1);  atomicAdd(&g_deg_in[d.w], 1);
    }
}

// exclusive scan of deg_in -> row_start; also norm_src from deg_out, cursor=0
__global__ void k_scan(int n) {
    __shared__ int part[1024];
    int t = threadIdx.x;
    int chunk = (((n + 1023) >> 10) + 3) & ~3;   // multiple of 4
    int beg = min(t * chunk, n);
    int end = min(beg + chunk, n);
    int own = 0;
    int i = beg;
    for (; i + 4 <= end; i += 4) {
        int4 v = *reinterpret_cast<const int4*>(&g_deg_in[i]);
        own += v.x + v.y + v.z + v.w;
    }
    for (; i < end; ++i) own += g_deg_in[i];
    part[t] = own;
    __syncthreads();
#pragma unroll
    for (int off = 1; off < 1024; off <<= 1) {
        int v = (t >= off) ? part[t - off] : 0;
        __syncthreads();
        part[t] += v;
        __syncthreads();
    }
    if (t == 1023) g_row_start[n] = part[1023];
    int run = part[t] - own;
    for (i = beg; i < end; ++i) {
        g_row_start[i] = run;
        run += g_deg_in[i];
        g_cursor[i] = 0;
        g_norm_src[i] = rsqrtf(fmaxf((float)g_deg_out[i], 1.0f));
    }
}

// CSR fill (int4 edges) + fp16 conversion h16 = fp16(x*norm_src)
__global__ void k_fill_half(const int* __restrict__ ei, const float* __restrict__ x,
                            int e4, int e, int n) {
    int i = blockIdx.x * blockDim.x + threadIdx.x;
    if (i < e4) {
        int4 s = reinterpret_cast<const int4*>(ei)[i];
        int4 d = reinterpret_cast<const int4*>(ei + e)[i];
        g_csr_src[g_row_start[d.x] + atomicAdd(&g_cursor[d.x], 1)] = s.x;
        g_csr_src[g_row_start[d.y] + atomicAdd(&g_cursor[d.y], 1)] = s.y;
        g_csr_src[g_row_start[d.z] + atomicAdd(&g_cursor[d.z], 1)] = s.z;
        g_csr_src[g_row_start[d.w] + atomicAdd(&g_cursor[d.w], 1)] = s.w;
    }
    int cvt_total = n * 32;
    if (i < cvt_total) {
        int node = i >> 5;
        float nm = g_norm_src[node];
        float4 v = reinterpret_cast<const float4*>(x)[i];
        __half2 h0 = __floats2half2_rn(v.x * nm, v.y * nm);
        __half2 h1 = __floats2half2_rn(v.z * nm, v.w * nm);
        uint2 o;
        o.x = *(uint32_t*)&h0;
        o.y = *(uint32_t*)&h1;
        g_h16[i] = o;
    }
}

// ---------------- aggregation: one warp per destination node ----------------
__global__ __launch_bounds__(256)
void k_agg(int n) {
    int warp = (blockIdx.x * blockDim.x + threadIdx.x) >> 5;
    int lane = threadIdx.x & 31;
    if (warp >= n) return;

    int beg = g_row_start[warp];
    int end = g_row_start[warp + 1];
    int deg = end - beg;

    float ax = 0.f, ay = 0.f, az = 0.f, aw = 0.f;

    int idx = beg;
    for (; idx + 4 <= end; idx += 4) {
        int s0 = g_csr_src[idx],     s1 = g_csr_src[idx + 1];
        int s2 = g_csr_src[idx + 2], s3 = g_csr_src[idx + 3];
        uint2 v0 = g_h16[(size_t)s0 * 32 + lane];
        uint2 v1 = g_h16[(size_t)s1 * 32 + lane];
        uint2 v2 = g_h16[(size_t)s2 * 32 + lane];
        uint2 v3 = g_h16[(size_t)s3 * 32 + lane];
        float2 f;
        f = __half22float2(*(__half2*)&v0.x); ax += f.x; ay += f.y;
        f = __half22float2(*(__half2*)&v0.y); az += f.x; aw += f.y;
        f = __half22float2(*(__half2*)&v1.x); ax += f.x; ay += f.y;
        f = __half22float2(*(__half2*)&v1.y); az += f.x; aw += f.y;
        f = __half22float2(*(__half2*)&v2.x); ax += f.x; ay += f.y;
        f = __half22float2(*(__half2*)&v2.y); az += f.x; aw += f.y;
        f = __half22float2(*(__half2*)&v3.x); ax += f.x; ay += f.y;
        f = __half22float2(*(__half2*)&v3.y); az += f.x; aw += f.y;
    }
    for (; idx < end; ++idx) {
        int s0 = g_csr_src[idx];
        uint2 v0 = g_h16[(size_t)s0 * 32 + lane];
        float2 f;
        f = __half22float2(*(__half2*)&v0.x); ax += f.x; ay += f.y;
        f = __half22float2(*(__half2*)&v0.y); az += f.x; aw += f.y;
    }

    float nd = rsqrtf(fmaxf((float)deg, 1.0f));
    uint4 t;
    t.x = f2tf32(ax * nd); t.y = f2tf32(ay * nd);
    t.z = f2tf32(az * nd); t.w = f2tf32(aw * nd);
    reinterpret_cast<uint4*>(g_agg)[(size_t)warp * 32 + lane] = t;
}

// ---------------- GEMM: out = relu(agg @ W + b), tf32 mma.sync --------------
// smem: bias 512B | A tile 128x132 u32 (67.6KB) | B fragments (64KB)
#define A_PITCH  132
#define SM_BIAS  0
#define SM_A     512
#define SM_BF    (512 + 128 * A_PITCH * 4)
#define SM_TOTAL (SM_BF + 16 * 16 * 32 * 2 * 4)

__global__ __launch_bounds__(256, 1)
void k_gemm(const float* __restrict__ Wm, const float* __restrict__ bias,
            float* __restrict__ out, int n) {
    extern __shared__ char smem[];
    float*    sBias = (float*)(smem + SM_BIAS);
    uint32_t* sA    = (uint32_t*)(smem + SM_A);
    uint2*    sBf   = (uint2*)(smem + SM_BF);

    int tid = threadIdx.x;
    int wid = tid >> 5;
    int lid = tid & 31;
    int rowBase = blockIdx.x * 128;

    if (tid < 128) sBias[tid] = bias[tid];

    // stage W (k-major [k][n]) into mma B-fragment layout
#pragma unroll
    for (int i = 0; i < 64; ++i) {
        int idx = tid + i * 256;
        int k = idx >> 7;
        int nn = idx & 127;
        int nt = nn >> 3, ks = k >> 3;
        int lane = ((nn & 7) << 2) | (k & 3);
        int slot = (k >> 2) & 1;
        ((uint32_t*)&sBf[(nt * 16 + ks) * 32 + lane])[slot] = f2tf32(Wm[idx]);
    }

    // stage A tile coalesced: 128 rows x 128 cols of tf32 bits from g_agg
#pragma unroll
    for (int i = 0; i < 16; ++i) {
        int fid = tid + i * 256;          // 0..4095
        int r = fid >> 5;                 // 0..127
        int cq = fid & 31;                // 0..31  (16B chunk)
        int grow = rowBase + r;
        uint4 v = make_uint4(0u, 0u, 0u, 0u);
        if (grow < n)
            v = *reinterpret_cast<const uint4*>(&g_agg[(size_t)grow * 128 + cq * 4]);
        *reinterpret_cast<uint4*>(&sA[r * A_PITCH + cq * 4]) = v;
    }
    __syncthreads();

    float acc[16][4];
#pragma unroll
    for (int nt = 0; nt < 16; ++nt)
#pragma unroll
        for (int q = 0; q < 4; ++q) acc[nt][q] = 0.f;

    int m0 = wid * 16 + (lid >> 2);       // fragment rows m0, m0+8
#pragma unroll
    for (int ks = 0; ks < 16; ++ks) {
        int k0 = ks * 8 + (lid & 3);
        uint32_t a0 = sA[m0 * A_PITCH + k0];
        uint32_t a1 = sA[(m0 + 8) * A_PITCH + k0];
        uint32_t a2 = sA[m0 * A_PITCH + k0 + 4];
        uint32_t a3 = sA[(m0 + 8) * A_PITCH + k0 + 4];
#pragma unroll
        for (int nt = 0; nt < 16; ++nt) {
            uint2 b = sBf[(nt * 16 + ks) * 32 + lid];
            mma_tf32(acc[nt], a0, a1, a2, a3, b.x, b.y);
        }
    }

    // epilogue: bias + relu
    int rA = rowBase + m0;
    int rB = rA + 8;
#pragma unroll
    for (int nt = 0; nt < 16; ++nt) {
        int col = nt * 8 + (lid & 3) * 2;
        float b0 = sBias[col], b1 = sBias[col + 1];
        if (rA < n) {
            float2 v;
            v.x = fmaxf(acc[nt][0] + b0, 0.f);
            v.y = fmaxf(acc[nt][1] + b1, 0.f);
            *(float2*)&out[(size_t)rA * 128 + col] = v;
        }
        if (rB < n) {
            float2 v;
            v.x = fmaxf(acc[nt][2] + b0, 0.f);
            v.y = fmaxf(acc[nt][3] + b1, 0.f);
            *(float2*)&out[(size_t)rB * 128 + col] = v;
        }
    }
}

// ---------------- launch ----------------------------------------------------
extern "C" void kernel_launch(void* const* d_in, const int* in_sizes, int n_in,
                              void* d_out, int out_size) {
    const float* x    = (const float*)d_in[0];
    const int*   ei   = (const int*)d_in[1];
    const float* Wm   = (const float*)d_in[2];
    const float* bias = (const float*)d_in[3];
    float* out = (float*)d_out;

    int n = in_sizes[0] / 128;   // 50000
    int e = in_sizes[1] / 2;     // 800000
    int n4 = (n + 3) / 4;
    int e4 = e / 4;              // 800000 % 4 == 0

    cudaFuncSetAttribute(k_gemm, cudaFuncAttributeMaxDynamicSharedMemorySize, SM_TOTAL);

    k_init<<<(n4 + 255) / 256, 256>>>(n4);
    k_count<<<(e4 + 255) / 256, 256>>>(ei, e4, e);
    k_scan<<<1, 1024>>>(n);
    int fh_threads = (n * 32 > e4) ? n * 32 : e4;
    k_fill_half<<<(fh_threads + 255) / 256, 256>>>(ei, x, e4, e, n);
    k_agg<<<(n * 32 + 255) / 256, 256>>>(n);
    k_gemm<<<(n + 127) / 128, 256, SM_TOTAL>>>(Wm, bias, out, n);
}

// round 6
// speedup vs baseline: 1.1731x; 1.1731x over previous
#include <cuda_runtime.h>
#include <cuda_fp16.h>
#include <cstdint>

#define N_MAX 50000
#define E_MAX 800000

// ---------------- scratch (__device__ globals; no allocs allowed) ----------
__device__ int      g_deg_in[N_MAX];
__device__ int      g_deg_out[N_MAX];
__device__ int      g_row_start[N_MAX + 1];
__device__ int      g_cursor[N_MAX];
__device__ int      g_csr_src[E_MAX];
__device__ float    g_norm_src[N_MAX];
__device__ uint2    g_h16[(size_t)N_MAX * 32];    // fp16 x*norm_src (4 halves each)
__device__ uint2    g_aggh[(size_t)N_MAX * 32];   // fp16 aggregated rows (4 halves each)

__device__ __forceinline__ void mma_f16(float c[4], uint32_t a0, uint32_t a1,
                                        uint32_t a2, uint32_t a3,
                                        uint32_t b0, uint32_t b1) {
    asm volatile(
        "mma.sync.aligned.m16n8k16.row.col.f32.f16.f16.f32 "
        "{%0,%1,%2,%3}, {%4,%5,%6,%7}, {%8,%9}, {%0,%1,%2,%3};"
        : "+f"(c[0]), "+f"(c[1]), "+f"(c[2]), "+f"(c[3])
        : "r"(a0), "r"(a1), "r"(a2), "r"(a3), "r"(b0), "r"(b1));
}

// ---------------- prep (identical to R4 measured context) -------------------
__global__ void k_init(int n) {
    int i = blockIdx.x * blockDim.x + threadIdx.x;
    if (i < n) { g_deg_in[i] = 0; g_deg_out[i] = 0; g_cursor[i] = 0; }
}

__global__ void k_count(const int* __restrict__ ei, int e) {
    int i = blockIdx.x * blockDim.x + threadIdx.x;
    if (i < e) {
        atomicAdd(&g_deg_out[ei[i]], 1);
        atomicAdd(&g_deg_in[ei[e + i]], 1);
    }
}

__global__ void k_scan(int n) {
    __shared__ int part[1024];
    int t = threadIdx.x;
    int chunk = (n + 1023) / 1024;
    int beg = min(t * chunk, n);
    int end = min(beg + chunk, n);
    int own = 0;
    for (int i = beg; i < end; ++i) own += g_deg_in[i];
    part[t] = own;
    __syncthreads();
#pragma unroll
    for (int off = 1; off < 1024; off <<= 1) {
        int v = (t >= off) ? part[t - off] : 0;
        __syncthreads();
        part[t] += v;
        __syncthreads();
    }
    if (t == 1023) g_row_start[n] = part[1023];
    int run = part[t] - own;
    for (int i = beg; i < end; ++i) {
        g_row_start[i] = run;
        run += g_deg_in[i];
        g_norm_src[i] = rsqrtf(fmaxf((float)g_deg_out[i], 1.0f));
    }
}

__global__ void k_fill_half(const int* __restrict__ ei, const float* __restrict__ x,
                            int e, int n) {
    int i = blockIdx.x * blockDim.x + threadIdx.x;
    if (i < e) {
        int s = ei[i];
        int d = ei[e + i];
        int pos = atomicAdd(&g_cursor[d], 1);
        g_csr_src[g_row_start[d] + pos] = s;
    }
    int cvt_total = n * 32;
    if (i < cvt_total) {
        int node = i >> 5;
        float nm = g_norm_src[node];
        float4 v = reinterpret_cast<const float4*>(x)[i];
        __half2 h0 = __floats2half2_rn(v.x * nm, v.y * nm);
        __half2 h1 = __floats2half2_rn(v.z * nm, v.w * nm);
        uint2 o;
        o.x = *(uint32_t*)&h0;
        o.y = *(uint32_t*)&h1;
        g_h16[i] = o;
    }
}

// ---------------- aggregation: one warp per destination node ----------------
__global__ __launch_bounds__(256)
void k_agg(int n) {
    int warp = (blockIdx.x * blockDim.x + threadIdx.x) >> 5;
    int lane = threadIdx.x & 31;
    if (warp >= n) return;

    int beg = g_row_start[warp];
    int end = g_row_start[warp + 1];
    int deg = end - beg;

    float ax = 0.f, ay = 0.f, az = 0.f, aw = 0.f;

    int idx = beg;
    for (; idx + 4 <= end; idx += 4) {
        int s0 = g_csr_src[idx],     s1 = g_csr_src[idx + 1];
        int s2 = g_csr_src[idx + 2], s3 = g_csr_src[idx + 3];
        uint2 v0 = g_h16[(size_t)s0 * 32 + lane];
        uint2 v1 = g_h16[(size_t)s1 * 32 + lane];
        uint2 v2 = g_h16[(size_t)s2 * 32 + lane];
        uint2 v3 = g_h16[(size_t)s3 * 32 + lane];
        float2 f;
        f = __half22float2(*(__half2*)&v0.x); ax += f.x; ay += f.y;
        f = __half22float2(*(__half2*)&v0.y); az += f.x; aw += f.y;
        f = __half22float2(*(__half2*)&v1.x); ax += f.x; ay += f.y;
        f = __half22float2(*(__half2*)&v1.y); az += f.x; aw += f.y;
        f = __half22float2(*(__half2*)&v2.x); ax += f.x; ay += f.y;
        f = __half22float2(*(__half2*)&v2.y); az += f.x; aw += f.y;
        f = __half22float2(*(__half2*)&v3.x); ax += f.x; ay += f.y;
        f = __half22float2(*(__half2*)&v3.y); az += f.x; aw += f.y;
    }
    for (; idx < end; ++idx) {
        int s0 = g_csr_src[idx];
        uint2 v0 = g_h16[(size_t)s0 * 32 + lane];
        float2 f;
        f = __half22float2(*(__half2*)&v0.x); ax += f.x; ay += f.y;
        f = __half22float2(*(__half2*)&v0.y); az += f.x; aw += f.y;
    }

    float nd = rsqrtf(fmaxf((float)deg, 1.0f));
    __half2 h0 = __floats2half2_rn(ax * nd, ay * nd);
    __half2 h1 = __floats2half2_rn(az * nd, aw * nd);
    uint2 o;
    o.x = *(uint32_t*)&h0;
    o.y = *(uint32_t*)&h1;
    g_aggh[(size_t)warp * 32 + lane] = o;
}

// ---------------- GEMM: out = relu(agg @ W + b), fp16 m16n8k16 mma ----------
// smem: bias 512B | A tile 128 x 136 halves (34KB) | B frags (32KB) => ~67KB
#define A_PITCH_H 136
#define SM_BIAS   0
#define SM_A      512
#define SM_BF     (512 + 128 * A_PITCH_H * 2)
#define SM_TOTAL  (SM_BF + 16 * 8 * 32 * 8)

__global__ __launch_bounds__(256, 2)
void k_gemm(const float* __restrict__ Wm, const float* __restrict__ bias,
            float* __restrict__ out, int n) {
    extern __shared__ char smem[];
    float*    sBias = (float*)(smem + SM_BIAS);
    __half*   sA    = (__half*)(smem + SM_A);
    uint2*    sBf   = (uint2*)(smem + SM_BF);

    int tid = threadIdx.x;
    int wid = tid >> 5;
    int lid = tid & 31;
    int rowBase = blockIdx.x * 128;

    if (tid < 128) sBias[tid] = bias[tid];

    // stage W (k-major [k][n]) into m16n8k16 B-fragment layout (col-major B = W^T)
    // frag group (nt, ks): n0 = nn&7 -> lane hi bits, k within 16 selects reg/half
#pragma unroll
    for (int i = 0; i < 64; ++i) {
        int idx = tid + i * 256;
        int k = idx >> 7;
        int nn = idx & 127;
        int nt = nn >> 3, ks = k >> 4;
        int klo = k & 15;
        int lane = ((nn & 7) << 2) | ((klo & 7) >> 1);
        int reg = klo >> 3;         // 0 -> .x, 1 -> .y
        int hs = klo & 1;           // half slot within 32-bit
        __half hv = __float2half_rn(Wm[idx]);
        ((__half*)&sBf[(nt * 8 + ks) * 32 + lane])[reg * 2 + hs] = hv;
    }

    // stage A tile coalesced: 128 rows x 128 halves from g_aggh
#pragma unroll
    for (int i = 0; i < 8; ++i) {
        int fid = tid + i * 256;          // 0..2047
        int r = fid >> 4;                 // 0..127
        int cq = fid & 15;                // 16B chunk (8 halves)
        int grow = rowBase + r;
        uint4 v = make_uint4(0u, 0u, 0u, 0u);
        if (grow < n)
            v = reinterpret_cast<const uint4*>(&g_aggh[(size_t)grow * 32])[cq];
        *reinterpret_cast<uint4*>(&sA[r * A_PITCH_H + cq * 8]) = v;
    }
    __syncthreads();

    float acc[16][4];
#pragma unroll
    for (int nt = 0; nt < 16; ++nt)
#pragma unroll
        for (int q = 0; q < 4; ++q) acc[nt][q] = 0.f;

    int m0 = wid * 16 + (lid >> 2);       // fragment rows m0, m0+8
#pragma unroll
    for (int ks = 0; ks < 8; ++ks) {
        int k0 = ks * 16 + (lid & 3) * 2;
        uint32_t a0 = *(const uint32_t*)&sA[m0 * A_PITCH_H + k0];
        uint32_t a1 = *(const uint32_t*)&sA[(m0 + 8) * A_PITCH_H + k0];
        uint32_t a2 = *(const uint32_t*)&sA[m0 * A_PITCH_H + k0 + 8];
        uint32_t a3 = *(const uint32_t*)&sA[(m0 + 8) * A_PITCH_H + k0 + 8];
#pragma unroll
        for (int nt = 0; nt < 16; ++nt) {
            uint2 b = sBf[(nt * 8 + ks) * 32 + lid];
            mma_f16(acc[nt], a0, a1, a2, a3, b.x, b.y);
        }
    }

    // epilogue: bias + relu
    int rA = rowBase + m0;
    int rB = rA + 8;
#pragma unroll
    for (int nt = 0; nt < 16; ++nt) {
        int col = nt * 8 + (lid & 3) * 2;
        float b0 = sBias[col], b1 = sBias[col + 1];
        if (rA < n) {
            float2 v;
            v.x = fmaxf(acc[nt][0] + b0, 0.f);
            v.y = fmaxf(acc[nt][1] + b1, 0.f);
            *(float2*)&out[(size_t)rA * 128 + col] = v;
        }
        if (rB < n) {
            float2 v;
            v.x = fmaxf(acc[nt][2] + b0, 0.f);
            v.y = fmaxf(acc[nt][3] + b1, 0.f);
            *(float2*)&out[(size_t)rB * 128 + col] = v;
        }
    }
}

// ---------------- launch ----------------------------------------------------
extern "C" void kernel_launch(void* const* d_in, const int* in_sizes, int n_in,
                              void* d_out, int out_size) {
    const float* x    = (const float*)d_in[0];
    const int*   ei   = (const int*)d_in[1];
    const float* Wm   = (const float*)d_in[2];
    const float* bias = (const float*)d_in[3];
    float* out = (float*)d_out;

    int n = in_sizes[0] / 128;   // 50000
    int e = in_sizes[1] / 2;     // 800000

    cudaFuncSetAttribute(k_gemm, cudaFuncAttributeMaxDynamicSharedMemorySize, SM_TOTAL);

    k_init<<<(n + 255) / 256, 256>>>(n);
    k_count<<<(e + 255) / 256, 256>>>(ei, e);
    k_scan<<<1, 1024>>>(n);
    int fh_threads = (n * 32 > e) ? n * 32 : e;
    k_fill_half<<<(fh_threads + 255) / 256, 256>>>(ei, x, e, n);
    k_agg<<<(n * 32 + 255) / 256, 256>>>(n);
    k_gemm<<<(n + 127) / 128, 256, SM_TOTAL>>>(Wm, bias, out, n);
}